// round 1
// baseline (speedup 1.0000x reference)
#include <cuda_runtime.h>
#include <math_constants.h>

#define BB 16
#define CC 256
#define RR 64
#define HW 16384
#define NPLANE (BB * CC)
#define NEG_SLOPE 0.01f

// Scratch (allocation-free rule: __device__ globals)
__device__ float g_avg_r[NPLANE];
__device__ float g_avg_i[NPLANE];
__device__ float g_max_r[NPLANE];
__device__ float g_max_i[NPLANE];
__device__ float g_gr[NPLANE];
__device__ float g_gi[NPLANE];

// ---------------------------------------------------------------------------
// Kernel 1: per-plane mean + max pooling over H*W for real and imag.
// One block per (b,c) plane. 256 threads, float4 loads (16 iters/thread).
// ---------------------------------------------------------------------------
__global__ __launch_bounds__(256) void pool_kernel(const float* __restrict__ xr,
                                                   const float* __restrict__ xi) {
    const int plane = blockIdx.x;
    const float4* pr = reinterpret_cast<const float4*>(xr + (size_t)plane * HW);
    const float4* pi = reinterpret_cast<const float4*>(xi + (size_t)plane * HW);

    float sr = 0.f, si = 0.f;
    float mr = -CUDART_INF_F, mi = -CUDART_INF_F;

#pragma unroll 4
    for (int i = threadIdx.x; i < HW / 4; i += 256) {
        float4 a = pr[i];
        float4 b = pi[i];
        sr += (a.x + a.y) + (a.z + a.w);
        si += (b.x + b.y) + (b.z + b.w);
        mr = fmaxf(mr, fmaxf(fmaxf(a.x, a.y), fmaxf(a.z, a.w)));
        mi = fmaxf(mi, fmaxf(fmaxf(b.x, b.y), fmaxf(b.z, b.w)));
    }

    // warp reduce
#pragma unroll
    for (int o = 16; o > 0; o >>= 1) {
        sr += __shfl_down_sync(0xFFFFFFFFu, sr, o);
        si += __shfl_down_sync(0xFFFFFFFFu, si, o);
        mr = fmaxf(mr, __shfl_down_sync(0xFFFFFFFFu, mr, o));
        mi = fmaxf(mi, __shfl_down_sync(0xFFFFFFFFu, mi, o));
    }

    __shared__ float s_sr[8], s_si[8], s_mr[8], s_mi[8];
    const int wid = threadIdx.x >> 5;
    const int lid = threadIdx.x & 31;
    if (lid == 0) { s_sr[wid] = sr; s_si[wid] = si; s_mr[wid] = mr; s_mi[wid] = mi; }
    __syncthreads();
    if (threadIdx.x == 0) {
        float tsr = s_sr[0], tsi = s_si[0], tmr = s_mr[0], tmi = s_mi[0];
#pragma unroll
        for (int w = 1; w < 8; w++) {
            tsr += s_sr[w]; tsi += s_si[w];
            tmr = fmaxf(tmr, s_mr[w]); tmi = fmaxf(tmi, s_mi[w]);
        }
        g_avg_r[plane] = tsr * (1.0f / HW);
        g_avg_i[plane] = tsi * (1.0f / HW);
        g_max_r[plane] = tmr;
        g_max_i[plane] = tmi;
    }
}

// ---------------------------------------------------------------------------
// Kernel 2: shared complex MLP on avg & max branches + complex sigmoid gate.
// One block per batch element (16 blocks), 256 threads.
// ---------------------------------------------------------------------------
__global__ __launch_bounds__(256) void gate_kernel(
    const float* __restrict__ w1r, const float* __restrict__ w1i,
    const float* __restrict__ b1r, const float* __restrict__ b1i,
    const float* __restrict__ w2r, const float* __restrict__ w2i,
    const float* __restrict__ b2r, const float* __restrict__ b2i) {
    const int b = blockIdx.x;
    const int t = threadIdx.x;

    __shared__ float s_in[4][CC];  // 0:avg_r 1:avg_i 2:max_r 3:max_i
    __shared__ float s_h[4][RR];   // 0:avg_hr 1:avg_hi 2:max_hr 3:max_hi

    s_in[0][t] = g_avg_r[b * CC + t];
    s_in[1][t] = g_avg_i[b * CC + t];
    s_in[2][t] = g_max_r[b * CC + t];
    s_in[3][t] = g_max_i[b * CC + t];
    __syncthreads();

    // Layer 1 + complex LeakyReLU: 128 tasks = {avg,max} x 64 hidden units
    if (t < 128) {
        const int which = t >> 6;       // 0 = avg, 1 = max
        const int r = t & 63;
        const float* zr = s_in[2 * which];
        const float* zi = s_in[2 * which + 1];
        float yr = b1r[r], yi = b1i[r];
#pragma unroll 8
        for (int c = 0; c < CC; c++) {
            const float wr = w1r[r * CC + c];
            const float wi = w1i[r * CC + c];
            const float zrc = zr[c], zic = zi[c];
            yr = fmaf(zrc, wr, fmaf(-zic, wi, yr));
            yi = fmaf(zrc, wi, fmaf(zic, wr, yi));
        }
        yr = (yr > 0.f) ? yr : NEG_SLOPE * yr;
        yi = (yi > 0.f) ? yi : NEG_SLOPE * yi;
        s_h[2 * which][r] = yr;
        s_h[2 * which + 1][r] = yi;
    }
    __syncthreads();

    // Layer 2 for both branches + sigmoid gate. Thread t = output channel.
    {
        float ar = b2r[t], ai = b2i[t];
        float mr = b2r[t], mi = b2i[t];
#pragma unroll 8
        for (int j = 0; j < RR; j++) {
            const float wr = w2r[t * RR + j];
            const float wi = w2i[t * RR + j];
            const float har = s_h[0][j], hai = s_h[1][j];
            const float hmr = s_h[2][j], hmi = s_h[3][j];
            ar = fmaf(har, wr, fmaf(-hai, wi, ar));
            ai = fmaf(har, wi, fmaf(hai, wr, ai));
            mr = fmaf(hmr, wr, fmaf(-hmi, wi, mr));
            mi = fmaf(hmr, wi, fmaf(hmi, wr, mi));
        }
        const float zr = ar + mr;
        const float zi = ai + mi;
        g_gr[b * CC + t] = 1.0f / (1.0f + expf(-zr));
        g_gi[b * CC + t] = 1.0f / (1.0f + expf(-zi));
    }
}

// ---------------------------------------------------------------------------
// Kernel 3: elementwise complex multiply x * gate -> out[2,B,C,H,W].
// One block per plane, float4 streaming.
// ---------------------------------------------------------------------------
__global__ __launch_bounds__(256) void apply_kernel(const float* __restrict__ xr,
                                                    const float* __restrict__ xi,
                                                    float* __restrict__ out) {
    const int plane = blockIdx.x;
    const float gr = g_gr[plane];
    const float gi = g_gi[plane];

    const float4* pr = reinterpret_cast<const float4*>(xr + (size_t)plane * HW);
    const float4* pi = reinterpret_cast<const float4*>(xi + (size_t)plane * HW);
    float4* po_r = reinterpret_cast<float4*>(out + (size_t)plane * HW);
    float4* po_i = reinterpret_cast<float4*>(out + (size_t)NPLANE * HW + (size_t)plane * HW);

#pragma unroll 4
    for (int i = threadIdx.x; i < HW / 4; i += 256) {
        float4 a = pr[i];
        float4 b = pi[i];
        float4 r, m;
        r.x = fmaf(a.x, gr, -b.x * gi);
        r.y = fmaf(a.y, gr, -b.y * gi);
        r.z = fmaf(a.z, gr, -b.z * gi);
        r.w = fmaf(a.w, gr, -b.w * gi);
        m.x = fmaf(a.x, gi, b.x * gr);
        m.y = fmaf(a.y, gi, b.y * gr);
        m.z = fmaf(a.z, gi, b.z * gr);
        m.w = fmaf(a.w, gi, b.w * gr);
        po_r[i] = r;
        po_i[i] = m;
    }
}

extern "C" void kernel_launch(void* const* d_in, const int* in_sizes, int n_in,
                              void* d_out, int out_size) {
    const float* xr  = (const float*)d_in[0];
    const float* xi  = (const float*)d_in[1];
    const float* w1r = (const float*)d_in[2];
    const float* w1i = (const float*)d_in[3];
    const float* b1r = (const float*)d_in[4];
    const float* b1i = (const float*)d_in[5];
    const float* w2r = (const float*)d_in[6];
    const float* w2i = (const float*)d_in[7];
    const float* b2r = (const float*)d_in[8];
    const float* b2i = (const float*)d_in[9];
    float* out = (float*)d_out;

    pool_kernel<<<NPLANE, 256>>>(xr, xi);
    gate_kernel<<<BB, 256>>>(w1r, w1i, b1r, b1i, w2r, w2i, b2r, b2i);
    apply_kernel<<<NPLANE, 256>>>(xr, xi, out);
}